// round 1
// baseline (speedup 1.0000x reference)
#include <cuda_runtime.h>

// ---------------------------------------------------------------------------
// Problem constants (match reference shapes)
// ---------------------------------------------------------------------------
#define EMAX 262144
#define TMAX 2097152
#define DD   128
#define DAA  64

typedef unsigned long long u64;

// Scratch (device globals; no allocations allowed)
__device__ float g_buf0[(size_t)EMAX * DD];    // 134 MB
__device__ float g_buf1[(size_t)EMAX * DD];    // 134 MB
__device__ float g_xdown[(size_t)EMAX * DAA];  // 67 MB
__device__ float g_agg[(size_t)EMAX * DAA];    // 67 MB
__device__ float g_wrbf[6 * DD];               // fused W_rbf1@W_rbf2

// ---------------------------------------------------------------------------
// Packed fp32x2 helpers (Blackwell packed-FMA path: 2x fp32 throughput)
// ---------------------------------------------------------------------------
__device__ __forceinline__ u64 pack2(float lo, float hi) {
    u64 r; asm("mov.b64 %0, {%1, %2};" : "=l"(r) : "f"(lo), "f"(hi)); return r;
}
__device__ __forceinline__ u64 bcast2(float a) {
    u64 r; asm("mov.b64 %0, {%1, %1};" : "=l"(r) : "f"(a)); return r;
}
__device__ __forceinline__ void unpack2(u64 v, float& lo, float& hi) {
    asm("mov.b64 {%0, %1}, %2;" : "=f"(lo), "=f"(hi) : "l"(v));
}
__device__ __forceinline__ void fma2(u64& acc, u64 a, u64 b) {
    asm("fma.rn.f32x2 %0, %1, %2, %0;" : "+l"(acc) : "l"(a), "l"(b));
}
__device__ __forceinline__ float swishf(float x) {
    return x * (1.0f / (1.0f + __expf(-x)));
}
__device__ __forceinline__ void red_add_v4(float* p, float4 v) {
    asm volatile("red.global.add.v4.f32 [%0], {%1, %2, %3, %4};"
                 :: "l"(p), "f"(v.x), "f"(v.y), "f"(v.z), "f"(v.w) : "memory");
}

// ---------------------------------------------------------------------------
// Utility kernels
// ---------------------------------------------------------------------------
__global__ void zero_kernel(float* __restrict__ p, int n) {
    int i = blockIdx.x * blockDim.x + threadIdx.x;
    if (i < n) p[i] = 0.0f;
}

// g_wrbf[6][128] = W_rbf1[6][8] @ W_rbf2[8][128]
__global__ void wrbf_kernel(const float* __restrict__ W1, const float* __restrict__ W2,
                            float* __restrict__ out) {
    int c = threadIdx.x;  // 0..127
    #pragma unroll
    for (int r = 0; r < 6; r++) {
        float s = 0.f;
        #pragma unroll
        for (int j = 0; j < 8; j++) s += W1[r * 8 + j] * W2[j * DD + c];
        out[r * DD + c] = s;
    }
}

// ---------------------------------------------------------------------------
// Generic fused GEMM: Y = [res +] swish(X@W [+ b]) [* rbf_gate]
//   X: [nrows, NI], W: [NI, NO] row-major, Y: [nrows, NO]
//   BM=128 rows/block, BN=NO (64 or 128) cols/block, 256 threads.
// ---------------------------------------------------------------------------
template <int NI, int NO, bool GATE, bool BIAS, bool RES>
__global__ __launch_bounds__(256)
void gemm_k(const float* __restrict__ X, const float* __restrict__ W,
            const float* __restrict__ bias, const float* __restrict__ res,
            const float* __restrict__ rbf, const float* __restrict__ Wrbf,
            float* __restrict__ Y, int nrows) {
    constexpr int BM = 128, BK = 32, BN = NO;
    constexpr int CT = BN / 8;        // column-threads (16 or 8)
    constexpr int RT = 256 / CT;      // row-threads    (16 or 32)
    constexpr int TM = BM / RT;       // rows per thread (8 or 4)

    __shared__ float sX[BM][BK];
    __shared__ float sW[BK][BN];
    __shared__ float sG[GATE ? 6 * BN : 1];

    const int tid = threadIdx.x;
    const int row0 = blockIdx.x * BM;
    const int tc = tid % CT;
    const int tr = tid / CT;

    if (GATE) {
        for (int i = tid; i < 6 * BN; i += 256) sG[i] = Wrbf[i];
    }

    u64 acc[TM][4];
    #pragma unroll
    for (int m = 0; m < TM; m++)
        #pragma unroll
        for (int n = 0; n < 4; n++) acc[m][n] = 0ull;

    for (int k0 = 0; k0 < NI; k0 += BK) {
        // X tile: BM x BK
        #pragma unroll
        for (int i = 0; i < (BM * BK) / (256 * 4); i++) {
            int idx = tid + i * 256;
            int r = idx / (BK / 4), c = idx % (BK / 4);
            int rr = row0 + r; if (rr >= nrows) rr = nrows - 1;
            *(float4*)&sX[r][c * 4] =
                *(const float4*)&X[(size_t)rr * NI + k0 + c * 4];
        }
        // W tile: BK x BN
        #pragma unroll
        for (int i = 0; i < (BK * BN) / (256 * 4); i++) {
            int idx = tid + i * 256;
            int r = idx / (BN / 4), c = idx % (BN / 4);
            *(float4*)&sW[r][c * 4] =
                *(const float4*)&W[(size_t)(k0 + r) * NO + c * 4];
        }
        __syncthreads();

        #pragma unroll
        for (int k = 0; k < BK; k++) {
            float4 b0 = *(const float4*)&sW[k][tc * 8];
            float4 b1 = *(const float4*)&sW[k][tc * 8 + 4];
            u64 bb[4];
            bb[0] = pack2(b0.x, b0.y); bb[1] = pack2(b0.z, b0.w);
            bb[2] = pack2(b1.x, b1.y); bb[3] = pack2(b1.z, b1.w);
            #pragma unroll
            for (int m = 0; m < TM; m++) {
                u64 am = bcast2(sX[tr * TM + m][k]);
                #pragma unroll
                for (int n = 0; n < 4; n++) fma2(acc[m][n], am, bb[n]);
            }
        }
        __syncthreads();
    }

    // Epilogue
    float bv[8];
    if (BIAS) {
        float4 t0 = *(const float4*)&bias[tc * 8];
        float4 t1 = *(const float4*)&bias[tc * 8 + 4];
        bv[0] = t0.x; bv[1] = t0.y; bv[2] = t0.z; bv[3] = t0.w;
        bv[4] = t1.x; bv[5] = t1.y; bv[6] = t1.z; bv[7] = t1.w;
    }

    #pragma unroll
    for (int m = 0; m < TM; m++) {
        int row = row0 + tr * TM + m;
        if (row >= nrows) continue;
        float v[8];
        #pragma unroll
        for (int n = 0; n < 4; n++) unpack2(acc[m][n], v[2 * n], v[2 * n + 1]);
        #pragma unroll
        for (int c = 0; c < 8; c++) {
            float t = v[c] + (BIAS ? bv[c] : 0.0f);
            v[c] = swishf(t);
        }
        if (GATE) {
            float rv[6];
            #pragma unroll
            for (int r = 0; r < 6; r++) rv[r] = rbf[(size_t)row * 6 + r];
            #pragma unroll
            for (int c = 0; c < 8; c++) {
                float g = 0.f;
                #pragma unroll
                for (int r = 0; r < 6; r++) g += rv[r] * sG[r * BN + tc * 8 + c];
                v[c] *= g;
            }
        }
        if (RES) {
            float4 r0 = *(const float4*)&res[(size_t)row * NO + tc * 8];
            float4 r1 = *(const float4*)&res[(size_t)row * NO + tc * 8 + 4];
            v[0] += r0.x; v[1] += r0.y; v[2] += r0.z; v[3] += r0.w;
            v[4] += r1.x; v[5] += r1.y; v[6] += r1.z; v[7] += r1.w;
        }
        *(float4*)&Y[(size_t)row * NO + tc * 8]     = make_float4(v[0], v[1], v[2], v[3]);
        *(float4*)&Y[(size_t)row * NO + tc * 8 + 4] = make_float4(v[4], v[5], v[6], v[7]);
    }
}

// ---------------------------------------------------------------------------
// Triplet kernel: for each triplet t
//   h   = sbf[t] @ W_sbf1          (42 -> 8)
//   g   = h @ W_sbf2               (8 -> 64)
//   val = x_down[expand[t]] * g
//   agg[reduce[t]] += val          (vector red.global)
// 64 triplets per 256-thread block; 4 threads x 16 channels per triplet.
// ---------------------------------------------------------------------------
#define TPB_TRIP 64
__global__ __launch_bounds__(256)
void triplet_kernel(const float* __restrict__ sbf, const int* __restrict__ expand,
                    const int* __restrict__ reduce, const float* __restrict__ Wsbf1,
                    const float* __restrict__ Wsbf2, const float* __restrict__ xdown,
                    float* __restrict__ agg, int Ttot) {
    __shared__ float s_sbf[TPB_TRIP * 42];
    __shared__ float s_h[TPB_TRIP * 9];     // stride 9 to dodge bank conflicts
    __shared__ float s_w1[42 * 8];
    __shared__ float s_w2[8 * 64];
    __shared__ int   s_ekj[TPB_TRIP];
    __shared__ int   s_eji[TPB_TRIP];

    const int tid  = threadIdx.x;
    const int base = blockIdx.x * TPB_TRIP;
    const int n_t  = min(TPB_TRIP, Ttot - base);

    for (int i = tid; i < 42 * 8; i += 256) s_w1[i] = Wsbf1[i];
    for (int i = tid; i < 8 * 64; i += 256) s_w2[i] = Wsbf2[i];
    for (int i = tid; i < n_t * 42; i += 256) s_sbf[i] = sbf[(size_t)base * 42 + i];
    if (tid < n_t) {
        s_ekj[tid] = expand[base + tid];
        s_eji[tid] = reduce[base + tid];
    }
    __syncthreads();

    // h = sbf_tile @ W_sbf1
    for (int w = tid; w < n_t * 8; w += 256) {
        int i = w >> 3, j = w & 7;
        float s = 0.f;
        #pragma unroll
        for (int k = 0; k < 42; k++) s += s_sbf[i * 42 + k] * s_w1[k * 8 + j];
        s_h[i * 9 + j] = s;
    }
    __syncthreads();

    const int trip = tid >> 2;
    const int c0   = (tid & 3) * 16;
    if (trip < n_t) {
        float h[8];
        #pragma unroll
        for (int j = 0; j < 8; j++) h[j] = s_h[trip * 9 + j];
        const int ekj = s_ekj[trip];
        const int eji = s_eji[trip];
        const float4* xp = (const float4*)(xdown + (size_t)ekj * DAA + c0);
        float* ap = agg + (size_t)eji * DAA + c0;
        #pragma unroll
        for (int q = 0; q < 4; q++) {
            float4 x = xp[q];
            int cb = c0 + q * 4;
            float g0 = 0.f, g1 = 0.f, g2 = 0.f, g3 = 0.f;
            #pragma unroll
            for (int j = 0; j < 8; j++) {
                float4 wv = *(const float4*)&s_w2[j * 64 + cb];
                float hj = h[j];
                g0 += hj * wv.x; g1 += hj * wv.y; g2 += hj * wv.z; g3 += hj * wv.w;
            }
            red_add_v4(ap + q * 4, make_float4(x.x * g0, x.y * g1, x.z * g2, x.w * g3));
        }
    }
}

// ---------------------------------------------------------------------------
// Host launcher
// ---------------------------------------------------------------------------
extern "C" void kernel_launch(void* const* d_in, const int* in_sizes, int n_in,
                              void* d_out, int out_size) {
    const float* m_input = (const float*)d_in[0];
    const float* rbf     = (const float*)d_in[1];
    const float* sbf     = (const float*)d_in[2];
    const int*   expand  = (const int*)d_in[3];
    const int*   reduce  = (const int*)d_in[4];
    const float* W_kj    = (const float*)d_in[5];
    const float* b_kj    = (const float*)d_in[6];
    const float* W_rbf1  = (const float*)d_in[7];
    const float* W_rbf2  = (const float*)d_in[8];
    const float* W_sbf1  = (const float*)d_in[9];
    const float* W_sbf2  = (const float*)d_in[10];
    const float* W_down  = (const float*)d_in[11];
    const float* W_up    = (const float*)d_in[12];
    const float* W_ji    = (const float*)d_in[13];
    const float* b_ji    = (const float*)d_in[14];
    const float* W_res_b = (const float*)d_in[15];
    const float* b_res_b = (const float*)d_in[16];
    const float* W_final = (const float*)d_in[17];
    const float* b_final = (const float*)d_in[18];
    const float* W_res_a = (const float*)d_in[19];
    const float* b_res_a = (const float*)d_in[20];
    float* out = (float*)d_out;

    const int E = in_sizes[0] / DD;
    const int T = in_sizes[3];

    float *buf0, *buf1, *xdown, *agg, *wrbf;
    cudaGetSymbolAddress((void**)&buf0, g_buf0);
    cudaGetSymbolAddress((void**)&buf1, g_buf1);
    cudaGetSymbolAddress((void**)&xdown, g_xdown);
    cudaGetSymbolAddress((void**)&agg, g_agg);
    cudaGetSymbolAddress((void**)&wrbf, g_wrbf);

    const int gblocks = (E + 127) / 128;
    const dim3 gthr(256);

    // 0) zero agg
    {
        int n = E * DAA;
        zero_kernel<<<(n + 255) / 256, 256>>>(agg, n);
    }
    // 1) fuse rbf projection weights
    wrbf_kernel<<<1, 128>>>(W_rbf1, W_rbf2, wrbf);

    // 2) A: buf0 = swish(m_input@W_kj + b_kj) * ((rbf@Wrbf1)@Wrbf2)
    gemm_k<128, 128, true, true, false><<<gblocks, gthr>>>(
        m_input, W_kj, b_kj, nullptr, rbf, wrbf, buf0, E);
    // 3) B: xdown = swish(buf0 @ W_down)
    gemm_k<128, 64, false, false, false><<<gblocks, gthr>>>(
        buf0, W_down, nullptr, nullptr, nullptr, nullptr, xdown, E);
    // 4) triplet gather/gate/scatter-sum
    triplet_kernel<<<(T + TPB_TRIP - 1) / TPB_TRIP, 256>>>(
        sbf, expand, reduce, W_sbf1, W_sbf2, xdown, agg, T);
    // 5) D1: buf1 = swish(agg @ W_up)
    gemm_k<64, 128, false, false, false><<<gblocks, gthr>>>(
        agg, W_up, nullptr, nullptr, nullptr, nullptr, buf1, E);
    // 6) D2: buf0 = swish(m_input@W_ji + b_ji) + buf1     (= m1)
    gemm_k<128, 128, false, true, true><<<gblocks, gthr>>>(
        m_input, W_ji, b_ji, buf1, nullptr, nullptr, buf0, E);
    // 7) E1: buf1 = swish(buf0 @ Wb[0] + bb[0])
    gemm_k<128, 128, false, true, false><<<gblocks, gthr>>>(
        buf0, W_res_b, b_res_b, nullptr, nullptr, nullptr, buf1, E);
    // 8) E2: buf1 = buf0 + swish(buf1 @ Wb[1] + bb[1])    (= m2, in-place X safe)
    gemm_k<128, 128, false, true, true><<<gblocks, gthr>>>(
        buf1, W_res_b + DD * DD, b_res_b + DD, buf0, nullptr, nullptr, buf1, E);
    // 9) F: buf0 = swish(buf1 @ W_final + b_final) + m_input  (= m3)
    gemm_k<128, 128, false, true, true><<<gblocks, gthr>>>(
        buf1, W_final, b_final, m_input, nullptr, nullptr, buf0, E);
    // 10) G1: buf1 = swish(buf0 @ Wa[0,0] + ba[0,0])
    gemm_k<128, 128, false, true, false><<<gblocks, gthr>>>(
        buf0, W_res_a, b_res_a, nullptr, nullptr, nullptr, buf1, E);
    // 11) G2: buf1 = buf0 + swish(buf1 @ Wa[0,1] + ba[0,1])   (= m4)
    gemm_k<128, 128, false, true, true><<<gblocks, gthr>>>(
        buf1, W_res_a + DD * DD, b_res_a + DD, buf0, nullptr, nullptr, buf1, E);
    // 12) H1: buf0 = swish(buf1 @ Wa[1,0] + ba[1,0])
    gemm_k<128, 128, false, true, false><<<gblocks, gthr>>>(
        buf1, W_res_a + 2 * DD * DD, b_res_a + 2 * DD, nullptr, nullptr, nullptr, buf0, E);
    // 13) H2: out = buf1 + swish(buf0 @ Wa[1,1] + ba[1,1])
    gemm_k<128, 128, false, true, true><<<gblocks, gthr>>>(
        buf0, W_res_a + 3 * DD * DD, b_res_a + 3 * DD, buf1, nullptr, nullptr, out, E);
}